// round 12
// baseline (speedup 1.0000x reference)
#include <cuda_runtime.h>

#define L_SEQ 1024
#define M_DIM 128

// Table layout (step-major, m-split for warp pairs), padded 2 steps:
//   per step i, half h (m in [64h,64h+64)), lane l (2 m: 64h+2l, 64h+2l+1):
//   float4 at ((i*2+h)*128 + l*4) = { W[m0], W[m1], Q[m0], Q[m1] }
//   W[m] = dlt[m,i] * prod_{j<i} e0[m,j],  Q[m] = dlt[m,i] / e0[m,i]
__device__ float g_tbl[(L_SEQ + 2) * 256];
__device__ float g_e0[L_SEQ * M_DIM];
__device__ float g_dl[L_SEQ * M_DIM];
__device__ float g_cp[8 * M_DIM];

typedef unsigned long long u64;

__device__ __forceinline__ u64 pk2(float lo, float hi) {
    u64 r; asm("mov.b64 %0,{%1,%2};" : "=l"(r) : "f"(lo), "f"(hi)); return r;
}
__device__ __forceinline__ void upk2(u64 v, float& lo, float& hi) {
    asm("mov.b64 {%0,%1},%2;" : "=f"(lo), "=f"(hi) : "l"(v));
}
__device__ __forceinline__ u64 mul2(u64 a, u64 b) {
    u64 r; asm("mul.rn.f32x2 %0,%1,%2;" : "=l"(r) : "l"(a), "l"(b)); return r;
}
__device__ __forceinline__ u64 add2(u64 a, u64 b) {
    u64 r; asm("add.rn.f32x2 %0,%1,%2;" : "=l"(r) : "l"(a), "l"(b)); return r;
}
// predicated: if (s) h = q*h + h
__device__ __forceinline__ void upd1(u64& h, u64 q, int s) {
    asm("{.reg .pred P; setp.ne.s32 P,%2,0; @P fma.rn.f32x2 %0,%1,%0,%0;}"
        : "+l"(h) : "l"(q), "r"(s));
}
__device__ __forceinline__ u64 shfl64_xor(unsigned mask, u64 v, int o) {
    double d = __longlong_as_double((long long)v);
    d = __shfl_xor_sync(mask, d, o);
    return (u64)__double_as_longlong(d);
}

// prepA: transpose eps [D,M,L] -> step-major e0 / dlt
__global__ void prepA(const float* __restrict__ eps) {
    int idx = blockIdx.x * blockDim.x + threadIdx.x;
    if (idx >= L_SEQ * M_DIM) return;
    int i = idx >> 7, m = idx & 127;
    float a = eps[(size_t)m * L_SEQ + i];
    float b = eps[(size_t)(M_DIM + m) * L_SEQ + i];
    g_e0[i * 128 + m] = a;
    g_dl[i * 128 + m] = b - a;
}

// prepB: per (m, chunk c of 128 steps) product of e0
__global__ void prepB() {
    int idx = blockIdx.x * blockDim.x + threadIdx.x;   // 0..1023
    int m = idx & 127, c = idx >> 7;
    float p = 1.f;
    #pragma unroll 8
    for (int t = 0; t < 128; t++)
        p *= g_e0[(c * 128 + t) * 128 + m];
    g_cp[c * 128 + m] = p;
}

// prepC: scan within chunk, write W and Q in the m-split interleaved layout
__global__ void prepC() {
    int idx = blockIdx.x * blockDim.x + threadIdx.x;   // 0..1023
    int m = idx & 127, c = idx >> 7;
    const int h = m >> 6, l = (m >> 1) & 31, sub = m & 1;
    float P = 1.f;
    for (int cc = 0; cc < c; cc++) P *= g_cp[cc * 128 + m];
    for (int t = 0; t < 128; t++) {
        int i = c * 128 + t;
        float e = g_e0[i * 128 + m];
        float d = g_dl[i * 128 + m];
        int base = (i * 2 + h) * 128 + l * 4;
        g_tbl[base + sub]     = d * P;                 // W
        g_tbl[base + 2 + sub] = __fdividef(d, e);      // Q
        P *= e;
    }
    if (c == 0) {   // zero pad steps (prefetch targets only)
        for (int pi = L_SEQ; pi < L_SEQ + 2; pi++) {
            int base = (pi * 2 + h) * 128 + l * 4;
            g_tbl[base + sub] = 0.f;
            g_tbl[base + 2 + sub] = 0.f;
        }
    }
}

#define WIN 16                 // window (steps) between reductions
#define ST1 17                 // u64 stride per step in stage-1 arrays (16 entries + pad)
#define A23 272                // arr23 offset (= WIN*ST1)
#define WBUF 544               // per-warp stage-1 u64 buffer

__global__ __launch_bounds__(128, 7)
void arqgps_kernel(const int* __restrict__ inp, float* __restrict__ out, int nrows) {
    __shared__ u64 st1[4][WBUF];        // stage-1 partials, per warp (17.4 KB)
    __shared__ u64 exch[2][4][32];      // cross-half exchange, parity double-buffered (2 KB)

    const unsigned FULL = 0xffffffffu;
    const int lane    = threadIdx.x & 31;
    const int wid     = threadIdx.x >> 5;
    const int rgLocal = wid >> 1;                     // row-group within block (0,1)
    const int half    = wid & 1;                      // m-half this warp owns
    const bool lo16   = (lane < 16);
    const int nrg     = nrows >> 2;                   // 4 rows per row-group
    const int rg_raw  = blockIdx.x * 2 + rgLocal;
    const bool live   = (rg_raw < nrg);
    const int rg      = live ? rg_raw : (nrg - 1);    // clamp; never early-exit

    // table pointer for (half, lane): element of step i at tp[i*64]
    const ulonglong2* __restrict__ tp =
        reinterpret_cast<const ulonglong2*>(g_tbl) + half * 32 + lane;

    const int* __restrict__ p0r = inp + (size_t)(4 * rg) * L_SEQ;
    const int* __restrict__ p1r = p0r + L_SEQ;
    const int* __restrict__ p2r = p1r + L_SEQ;
    const int* __restrict__ p3r = p2r + L_SEQ;

    const u64 one2 = pk2(1.f, 1.f);
    u64 H0 = one2, H1 = one2, H2 = one2, H3 = one2;   // 2 m per row

    // smem bases
    u64* const wp = &st1[wid][(lo16 ? 0 : A23) + (lane & 15)];          // writer
    const u64* const rb = &st1[wid][(lo16 ? 0 : A23) + (lane & 15) * ST1]; // reader

    // lse identity: row = 2*(lane>>4) + half, step-in-window = lane&15
    const int lserow = ((lane >> 4) << 1) + half;
    const int kk     = lane & 15;

    float acc = 0.f;
    int   c1m = 0;                                    // 1-count for MY lse row
    int   par = 0;                                    // exchange parity

    // depth-2 pipeline
    ulonglong2 Tc = tp[0], Tn = tp[64];

    unsigned b0 = __ballot_sync(FULL, __ldg(p0r + lane) & 1);
    unsigned b1 = __ballot_sync(FULL, __ldg(p1r + lane) & 1);
    unsigned b2 = __ballot_sync(FULL, __ldg(p2r + lane) & 1);
    unsigned b3 = __ballot_sync(FULL, __ldg(p3r + lane) & 1);

    for (int i0 = 0; i0 < L_SEQ; i0 += 32) {
        const int nx = i0 + 32;
        const bool more = (nx < L_SEQ);
        const unsigned n0 = __ballot_sync(FULL, (more ? __ldg(p0r + nx + lane) : 0) & 1);
        const unsigned n1 = __ballot_sync(FULL, (more ? __ldg(p1r + nx + lane) : 0) & 1);
        const unsigned n2 = __ballot_sync(FULL, (more ? __ldg(p2r + nx + lane) : 0) & 1);
        const unsigned n3 = __ballot_sync(FULL, (more ? __ldg(p3r + nx + lane) : 0) & 1);
        const unsigned mybits = (lserow == 0) ? b0 : (lserow == 1) ? b1
                              : (lserow == 2) ? b2 : b3;

        #pragma unroll
        for (int h = 0; h < 2; h++) {
            const ulonglong2* __restrict__ bb = tp + (size_t)(i0 + h * WIN) * 64;

            // ---- write phase: 16 steps ----
            #pragma unroll
            for (int t = 0; t < WIN; t++) {
                const int k = h * WIN + t;
                ulonglong2 T2 = bb[(t + 2) * 64];      // prefetch step+2 (pad-safe)

                const u64 Wv = Tc.x, Qv = Tc.y;
                u64 q0 = mul2(Wv, H0), q1 = mul2(Wv, H1);
                u64 q2 = mul2(Wv, H2), q3 = mul2(Wv, H3);

                upd1(H0, Qv, (int)((b0 >> k) & 1u));
                upd1(H1, Qv, (int)((b1 >> k) & 1u));
                upd1(H2, Qv, (int)((b2 >> k) & 1u));
                upd1(H3, Qv, (int)((b3 >> k) & 1u));

                float f0, f1, f2, f3, f4, f5, f6, f7;
                upk2(q0, f0, f1); upk2(q1, f2, f3);
                upk2(q2, f4, f5); upk2(q3, f6, f7);
                u64 pk01 = pk2(f0 + f1, f2 + f3);      // (row0, row1) partial
                u64 pk23 = pk2(f4 + f5, f6 + f7);      // (row2, row3)

                // lane-pair combine across xor-16: halves entries per step
                u64 send = lo16 ? pk23 : pk01;
                u64 keep = lo16 ? pk01 : pk23;
                u64 comb = add2(keep, shfl64_xor(FULL, send, 16));
                wp[t * ST1] = comb;

                Tc = Tn; Tn = T2;
            }
            __syncwarp();

            // ---- stage 1: own-warp reduction (16 entries for my (pair, step)) ----
            u64 s0 = rb[0], s1 = rb[1], s2 = rb[2], s3 = rb[3];
            #pragma unroll
            for (int l = 4; l < 16; l += 4) {
                s0 = add2(s0, rb[l]);
                s1 = add2(s1, rb[l + 1]);
                s2 = add2(s2, rb[l + 2]);
                s3 = add2(s3, rb[l + 3]);
            }
            u64 halfsum = add2(add2(s0, s1), add2(s2, s3));

            // ---- stage 2: cross-half exchange ----
            exch[par][wid][lane] = halfsum;
            asm volatile("bar.sync %0, 64;" :: "r"(1 + rgLocal) : "memory");
            u64 fullsum = add2(halfsum, exch[par][wid ^ 1][lane]);
            par ^= 1;

            float dlo, dhi; upk2(fullsum, dlo, dhi);
            const float dxt = (lserow & 1) ? dhi : dlo;

            // lse for (row = lserow, step = i0 + h*16 + kk)
            const unsigned bw = (mybits >> (h * WIN)) & 0xffffu;
            const int s   = (int)((bw >> kk) & 1u);
            const int c1i = c1m + __popc(bw & ((1u << kk) - 1u));
            const int i   = i0 + h * WIN + kk;

            const float sgn = s ? dxt : -dxt;
            const float contrib = fminf(0.f, sgn)
                                - 0.5f * __logf(1.f + __expf(-2.f * fabsf(dxt)));
            const bool dead_other = s ? ((i - c1i) >= 512) : (c1i >= 512);
            acc += dead_other ? 0.f : contrib;
            c1m += __popc(bw);

            __syncwarp();     // own-array readers done before next window's writes
        }

        b0 = n0; b1 = n1; b2 = n2; b3 = n3;
    }

    // sum acc across the 16 lanes owning each lse row (xor < 16 stays in group)
    acc += __shfl_xor_sync(FULL, acc, 1);
    acc += __shfl_xor_sync(FULL, acc, 2);
    acc += __shfl_xor_sync(FULL, acc, 4);
    acc += __shfl_xor_sync(FULL, acc, 8);

    // warp half writes rows {half, 2+half}: lane 0 -> row half, lane 16 -> row 2+half
    if (live && (lane & 15) == 0) out[4 * rg + lserow] = acc;
}

extern "C" void kernel_launch(void* const* d_in, const int* in_sizes, int n_in,
                              void* d_out, int out_size) {
    const int*   inp = nullptr;
    const float* eps = nullptr;
    int rows = 0;
    if (in_sizes[0] == 2 * M_DIM * L_SEQ) {
        eps = (const float*)d_in[0];
        inp = (const int*)d_in[1];
        rows = in_sizes[1] / L_SEQ;
    } else {
        inp = (const int*)d_in[0];
        eps = (const float*)d_in[1];
        rows = in_sizes[0] / L_SEQ;
    }

    { int n = L_SEQ * M_DIM; prepA<<<(n + 255) / 256, 256>>>(eps); }
    prepB<<<4, 256>>>();
    prepC<<<4, 256>>>();
    {
        // 2 row-groups (8 rows) per 128-thread block; warp pair per row-group
        int nrg = rows / 4;
        int grid = (nrg + 1) / 2;
        arqgps_kernel<<<grid, 128>>>(inp, (float*)d_out, rows);
    }
}

// round 13
// speedup vs baseline: 1.1824x; 1.1824x over previous
#include <cuda_runtime.h>

#define L_SEQ 1024
#define M_DIM 128

// Final table, step-major, padded two steps (prefetch depth 2):
//   per step i: floats [0..127]   W[m] = dlt[m,i] * P0[m,i]   (P0 = prod_{j<i} e0[m,j])
//               floats [128..255] q[m] = dlt[m,i] / e0[m,i]
__device__ float g_tbl[(L_SEQ + 2) * 256];
__device__ float g_e0[L_SEQ * M_DIM];
__device__ float g_dl[L_SEQ * M_DIM];
__device__ float g_cp[8 * M_DIM];

typedef unsigned long long u64;

__device__ __forceinline__ u64 pk2(float lo, float hi) {
    u64 r; asm("mov.b64 %0,{%1,%2};" : "=l"(r) : "f"(lo), "f"(hi)); return r;
}
__device__ __forceinline__ void upk2(u64 v, float& lo, float& hi) {
    asm("mov.b64 {%0,%1},%2;" : "=f"(lo), "=f"(hi) : "l"(v));
}
__device__ __forceinline__ u64 fma2(u64 a, u64 b, u64 c) {
    u64 r; asm("fma.rn.f32x2 %0,%1,%2,%3;" : "=l"(r) : "l"(a), "l"(b), "l"(c)); return r;
}
__device__ __forceinline__ u64 mul2(u64 a, u64 b) {
    u64 r; asm("mul.rn.f32x2 %0,%1,%2;" : "=l"(r) : "l"(a), "l"(b)); return r;
}
__device__ __forceinline__ u64 add2(u64 a, u64 b) {
    u64 r; asm("add.rn.f32x2 %0,%1,%2;" : "=l"(r) : "l"(a), "l"(b)); return r;
}
// predicated: if (s) { h0 = q0*h0 + h0; h1 = q1*h1 + h1; }
__device__ __forceinline__ void upd2(u64& h0, u64& h1, u64 q0, u64 q1, int s) {
    asm("{.reg .pred P; setp.ne.s32 P,%4,0;"
        "@P fma.rn.f32x2 %0,%2,%0,%0;"
        "@P fma.rn.f32x2 %1,%3,%1,%1;}"
        : "+l"(h0), "+l"(h1) : "l"(q0), "l"(q1), "r"(s));
}
__device__ __forceinline__ u64 shfl64_xor(unsigned mask, u64 v, int o) {
    double d = __longlong_as_double((long long)v);
    d = __shfl_xor_sync(mask, d, o);
    return (u64)__double_as_longlong(d);
}

// prepA: transpose eps [D,M,L] -> step-major e0 / dlt
__global__ void prepA(const float* __restrict__ eps) {
    int idx = blockIdx.x * blockDim.x + threadIdx.x;
    if (idx >= L_SEQ * M_DIM) return;
    int i = idx >> 7, m = idx & 127;
    float a = eps[(size_t)m * L_SEQ + i];
    float b = eps[(size_t)(M_DIM + m) * L_SEQ + i];
    g_e0[i * 128 + m] = a;
    g_dl[i * 128 + m] = b - a;
}

// prepB: per (m, chunk c of 128 steps) product of e0
__global__ void prepB() {
    int idx = blockIdx.x * blockDim.x + threadIdx.x;   // 0..1023
    int m = idx & 127, c = idx >> 7;
    float p = 1.f;
    #pragma unroll 8
    for (int t = 0; t < 128; t++)
        p *= g_e0[(c * 128 + t) * 128 + m];
    g_cp[c * 128 + m] = p;
}

// prepC: scan within chunk, write W and q; zero the 2 pad steps
__global__ void prepC() {
    int idx = blockIdx.x * blockDim.x + threadIdx.x;   // 0..1023
    int m = idx & 127, c = idx >> 7;
    float P = 1.f;
    for (int cc = 0; cc < c; cc++) P *= g_cp[cc * 128 + m];
    for (int t = 0; t < 128; t++) {
        int i = c * 128 + t;
        float e = g_e0[i * 128 + m];
        float d = g_dl[i * 128 + m];
        g_tbl[i * 256 + m]       = d * P;
        g_tbl[i * 256 + 128 + m] = __fdividef(d, e);
        P *= e;
    }
    if (c == 0) {
        g_tbl[L_SEQ * 256 + m] = 0.f;       g_tbl[L_SEQ * 256 + 128 + m] = 0.f;
        g_tbl[(L_SEQ + 1) * 256 + m] = 0.f; g_tbl[(L_SEQ + 1) * 256 + 128 + m] = 0.f;
    }
}

#define WIN 16                 // reduction window (steps)
#define ST 34                  // u64 stride per step (even -> 16B alignment for LDS.128)
#define WROW 546               // per-warp u64 count (16*34 + 2 pad; 546*8 divisible by 16)

__global__ __launch_bounds__(128, 7)
void arqgps_kernel(const int* __restrict__ inp, float* __restrict__ out, int nrows) {
    __shared__ alignas(16) u64 sp[4][WROW];      // 4 warps x 4368 B = 17.5 KB
    const unsigned FULL = 0xffffffffu;
    const int lane = threadIdx.x & 31;
    const int wid  = threadIdx.x >> 5;
    const int nrg  = nrows >> 1;                 // one row-pair per warp
    const int rg_raw = blockIdx.x * 4 + wid;
    const bool live = (rg_raw < nrg);
    const int rg = live ? rg_raw : (nrg - 1);    // clamp; never early-exit (ballots!)

    const ulonglong2* __restrict__ tb = reinterpret_cast<const ulonglong2*>(g_tbl);
    const int* __restrict__ i0p = inp + (size_t)(2 * rg) * L_SEQ;
    const int* __restrict__ i1p = i0p + L_SEQ;

    const u64 one2 = pk2(1.f, 1.f);
    u64 H0[2] = {one2, one2}, H1[2] = {one2, one2};   // 4 m per row

    // this lane finalizes (row = wrow, window-step = wstep); reads half the entries
    const int wstep = lane & 15;
    const int wrow  = lane >> 4;

    u64* const wp = &sp[wid][lane];              // writer base: wp[t*ST]
    // reader: lane j sums entries [16*wrow .. 16*wrow+15] of step wstep (8 x LDS.128)
    const ulonglong2* const rb =
        reinterpret_cast<const ulonglong2*>(&sp[wid][wstep * ST + 16 * wrow]);

    float acc = 0.f;
    int   c1m = 0;                               // 1-count for MY row before window

    // depth-2 tile pipeline
    ulonglong2 Wc = tb[lane],      Qc = tb[32 + lane];
    ulonglong2 Wn = tb[64 + lane], Qn = tb[96 + lane];

    unsigned bits0 = __ballot_sync(FULL, __ldg(i0p + lane) & 1);   // s for 32 steps, row0
    unsigned bits1 = __ballot_sync(FULL, __ldg(i1p + lane) & 1);   // row1

    for (int i0 = 0; i0 < L_SEQ; i0 += 32) {
        const int nx = i0 + 32;
        const int iv0n = (nx < L_SEQ) ? __ldg(i0p + nx + lane) : 0;
        const int iv1n = (nx < L_SEQ) ? __ldg(i1p + nx + lane) : 0;
        const unsigned bn0 = __ballot_sync(FULL, iv0n & 1);
        const unsigned bn1 = __ballot_sync(FULL, iv1n & 1);

        #pragma unroll
        for (int h = 0; h < 2; h++) {
            // ---- write phase: 16 steps, one STS.64 each, zero cross-lane deps ----
            #pragma unroll
            for (int t = 0; t < WIN; t++) {
                const int k = h * WIN + t;
                const int i = i0 + k;
                ulonglong2 W2 = tb[(size_t)(i + 2) * 64 + lane];
                ulonglong2 Q2 = tb[(size_t)(i + 2) * 64 + 32 + lane];

                u64 p0 = fma2(Wc.y, H0[1], mul2(Wc.x, H0[0]));   // row0, 4 m packed
                u64 p1 = fma2(Wc.y, H1[1], mul2(Wc.x, H1[0]));   // row1

                upd2(H0[0], H0[1], Qc.x, Qc.y, (int)((bits0 >> k) & 1u));
                upd2(H1[0], H1[1], Qc.x, Qc.y, (int)((bits1 >> k) & 1u));

                float a0, a1, a2, a3;
                upk2(p0, a0, a1); upk2(p1, a2, a3);
                wp[t * ST] = pk2(a0 + a1, a2 + a3);              // (row0, row1) partial

                Wc = Wn; Qc = Qn; Wn = W2; Qn = Q2;
            }
            __syncwarp();

            // ---- read phase: lane j sums its HALF (16 entries) of step (j&15),
            //      then one 64-bit xor-16 shuffle completes the 32-entry sum ----
            ulonglong2 L0 = rb[0], L1 = rb[1], L2 = rb[2], L3 = rb[3];
            ulonglong2 L4 = rb[4], L5 = rb[5], L6 = rb[6], L7 = rb[7];
            u64 s0 = add2(L0.x, L0.y), s1 = add2(L1.x, L1.y);
            u64 s2 = add2(L2.x, L2.y), s3 = add2(L3.x, L3.y);
            s0 = add2(s0, add2(L4.x, L4.y));
            s1 = add2(s1, add2(L5.x, L5.y));
            s2 = add2(s2, add2(L6.x, L6.y));
            s3 = add2(s3, add2(L7.x, L7.y));
            u64 half_ = add2(add2(s0, s1), add2(s2, s3));
            u64 st = add2(half_, shfl64_xor(FULL, half_, 16));
            float dr0, dr1; upk2(st, dr0, dr1);
            const float dxt = wrow ? dr1 : dr0;

            // lse for (row = wrow, step = i0 + h*16 + wstep)
            const unsigned bw = ((wrow ? bits1 : bits0) >> (h * WIN)) & 0xffffu;
            const int s   = (int)((bw >> wstep) & 1u);
            const int c1i = c1m + __popc(bw & ((1u << wstep) - 1u));
            const int i   = i0 + h * WIN + wstep;

            const float sgn = s ? dxt : -dxt;
            const float contrib = fminf(0.f, sgn)
                                - 0.5f * __logf(1.f + __expf(-2.f * fabsf(dxt)));
            const bool dead_other = s ? ((i - c1i) >= 512) : (c1i >= 512);
            acc += dead_other ? 0.f : contrib;

            c1m += __popc(bw);
            __syncwarp();                        // writers of next window wait for readers
        }

        bits0 = bn0; bits1 = bn1;
    }

    // sum acc across the 16 lanes owning each row (xor < 16 stays in-group)
    acc += __shfl_xor_sync(FULL, acc, 1);
    acc += __shfl_xor_sync(FULL, acc, 2);
    acc += __shfl_xor_sync(FULL, acc, 4);
    acc += __shfl_xor_sync(FULL, acc, 8);

    if (live && (lane & 15) == 0) out[2 * rg + wrow] = acc;
}

extern "C" void kernel_launch(void* const* d_in, const int* in_sizes, int n_in,
                              void* d_out, int out_size) {
    const int*   inp = nullptr;
    const float* eps = nullptr;
    int rows = 0;
    if (in_sizes[0] == 2 * M_DIM * L_SEQ) {
        eps = (const float*)d_in[0];
        inp = (const int*)d_in[1];
        rows = in_sizes[1] / L_SEQ;
    } else {
        inp = (const int*)d_in[0];
        eps = (const float*)d_in[1];
        rows = in_sizes[0] / L_SEQ;
    }

    { int n = L_SEQ * M_DIM; prepA<<<(n + 255) / 256, 256>>>(eps); }
    prepB<<<4, 256>>>();
    prepC<<<4, 256>>>();
    {
        // one warp per row-pair; 4 warps (8 rows) per 128-thread block
        int nrg = rows / 2;
        int grid = (nrg + 3) / 4;
        arqgps_kernel<<<grid, 128>>>(inp, (float*)d_out, rows);
    }
}